// round 9
// baseline (speedup 1.0000x reference)
#include <cuda_runtime.h>
#include <math.h>

typedef unsigned long long u64;
typedef unsigned short u16;
typedef unsigned char u8;

#define NN 4096
#define MM 20
#define HH 16
#define NX 32
#define NY 18
#define NLAB 3
#define NCELL (NLAB*NX*NY)   /* 1728 */
#define CAP 64
#define CAPC 28
#define SCAP 40960           /* shared CSR capacity (entries) */
#define NB 16
#define NT 1024
#define PI_F 3.14159274101257324f
#define QPI_F 0.785398185253143311f
#define COND 0.2f
#define IOUT 0.3f

// ---------------- global scratch ----------------
__device__ u64    g_tick;             // monotone ticket barrier counter (never reset)
__device__ int    g_bcnt[NN];         // bucket counts
__device__ int    g_bstart[NN];       // bucket starts
__device__ int    g_bcur[NN];         // bucket cursors
__device__ u64    g_keys[NN];
__device__ int    g_binv[NB];
__device__ int    g_binvoff[NB];
__device__ int    g_rank[NN];
__device__ int    g_vt;
__device__ float  g_b7[NN*7];
__device__ float4 g_bev[NN];
__device__ float  g_area[NN];
__device__ int    g_cellid[NN];
__device__ int    g_cellcnt[NCELL];
__device__ u16    g_cellbox[NCELL*CAPC];
__device__ u16    g_pred[NN*CAP];
__device__ u16    g_succ[NN*CAP];
__device__ int    g_npred[NN], g_nsucc[NN];
__device__ int    g_nwork;
__device__ int    g_work[2048];
__device__ int    g_wcnt[2048];
__device__ u16    g_wmem[2048*MM];

// ---------------- dynamic shared layout (bytes) ----------------
#define A_TEMP  0            /* int[1024]  4096  : scans / warp sums      */
#define F_OFFS  4096         /* int[4097]  16388 -> pad                    */
#define F_PD    20488        /* u16[SCAP]  81920                           */
#define F_STS   102408       /* u8 [4096]  4096                            */
#define F_SBY   106504       /* u16[4096]  8192                            */
#define F_FL0   114696       /* u16[4096]  8192                            */
#define F_FL1   122888       /* u16[4096]  8192                            */
#define SMEM_DYN 131080

// ---------------- replay-safe ticket grid barrier ----------------
__device__ __forceinline__ void gridbar() {
    __syncthreads();
    if (threadIdx.x == 0) {
        __threadfence();
        u64 my  = atomicAdd(&g_tick, 1ULL) + 1ULL;
        u64 tgt = ((my + NB - 1) / NB) * NB;
        while (*((volatile u64*)&g_tick) < tgt) { __nanosleep(32); }
        __threadfence();
    }
    __syncthreads();
}

__device__ __forceinline__ unsigned score_key(float f) {
    unsigned u = __float_as_uint(f) | 0x80000000u;
    return ~u;   // ascending key == descending f (f > 0)
}

__global__ __launch_bounds__(NT, 1) void k_all(
    const float* __restrict__ pb, const float* __restrict__ ps,
    const int* __restrict__ pl,
    const float* __restrict__ w1, const float* __restrict__ b1,
    const float* __restrict__ w2, const float* __restrict__ b2,
    const float* __restrict__ w3, const float* __restrict__ b3,
    float* __restrict__ out)
{
    extern __shared__ char sm[];
    int* temp = (int*)(sm + A_TEMP);
    __shared__ float s_w1[MM*HH], s_w2[HH*HH], s_w3[HH], s_b1[HH], s_b2[HH], s_b3v;
    __shared__ int s_useg, s_nf, s_nn;

    const int t = threadIdx.x;
    const int bid = blockIdx.x;
    const int lane = t & 31;

    // merge weights -> static shared (used in P4)
    for (int k = t; k < MM*HH; k += NT) s_w1[k] = w1[k];
    for (int k = t; k < HH*HH; k += NT) s_w2[k] = w2[k];
    if (t < HH) { s_w3[t] = w3[t]; s_b1[t] = b1[t]; s_b2[t] = b2[t]; }
    if (t == 0) s_b3v = b3[0];

    // ================= Pz: zero accumulators (grid-wide) =================
    {
        int g = bid * NT + t;
        if (g < NN) g_bcnt[g] = 0;
        if (g < NCELL) g_cellcnt[g] = 0;
        if (g == 0) g_nwork = 0;
    }
    gridbar();

    // ================= P0a: bucket histogram + per-block invalid counts ========
    {
        int flag = 0;
        if (t < 256) {
            int idx = bid * 256 + t;
            float f = ps[idx];
            if (f > COND) {
                int b = 4096 - (int)(f * 4096.0f);
                b = min(max(b, 0), 4095);
                atomicAdd(&g_bcnt[b], 1);
            } else flag = 1;
        }
        unsigned m = __ballot_sync(0xFFFFFFFFu, flag);
        if (lane == 0) temp[t >> 5] = __popc(m);
        __syncthreads();
        if (t == 0) {
            int s = 0;
            for (int k = 0; k < 8; k++) s += temp[k];
            g_binv[bid] = s;
        }
    }
    gridbar();

    // ================= P0b: bucket scan (block 0 only) =================
    if (bid == 0) {
        const int base = t * 4;
        int c4[4]; int s0 = 0;
        #pragma unroll
        for (int k = 0; k < 4; k++) { c4[k] = g_bcnt[base + k]; s0 += c4[k]; }
        temp[t] = s0;
        __syncthreads();
        for (int off = 1; off < NT; off <<= 1) {
            int v = (t >= off) ? temp[t - off] : 0;
            __syncthreads();
            temp[t] += v;
            __syncthreads();
        }
        if (t == 0) g_vt = temp[NT-1];
        int run = (t == 0) ? 0 : temp[t - 1];
        #pragma unroll
        for (int k = 0; k < 4; k++) {
            g_bstart[base + k] = run;
            g_bcur[base + k]   = run;
            run += c4[k];
        }
        if (t == 0) {
            int s = 0;
            for (int k = 0; k < NB; k++) { int c = g_binv[k]; g_binvoff[k] = s; s += c; }
        }
    }
    gridbar();

    // ================= P0c: scatter (valid -> buckets, invalid -> tail ranks) ==
    {
        int flag = 0; unsigned key = 0; int b = -1;
        int idx = bid * 256 + t;
        if (t < 256) {
            float f = ps[idx];
            if (f > COND) {
                key = score_key(f);
                b = 4096 - (int)(f * 4096.0f);
                b = min(max(b, 0), 4095);
            } else flag = 1;
        }
        unsigned m = __ballot_sync(0xFFFFFFFFu, flag);
        int lanep = __popc(m & ((1u << lane) - 1));
        if (lane == 0) temp[t >> 5] = __popc(m);
        __syncthreads();
        if (t == 0) {
            int s = 0;
            for (int k = 0; k < 8; k++) { int c = temp[k]; temp[k] = s; s += c; }
        }
        __syncthreads();
        if (t < 256) {
            if (!flag) {
                int pos = atomicAdd(&g_bcur[b], 1);
                g_keys[pos] = ((u64)key << 32) | (unsigned)idx;
            } else {
                g_rank[idx] = g_vt + g_binvoff[bid] + temp[t >> 5] + lanep;
            }
        }
    }
    gridbar();

    // ================= P0d: per-bucket sort + rank write (grid-wide) ===========
    {
        int b = bid + NB * t;           // one bucket per thread (t<256 effective)
        if (b < NN) {
            int c = g_bcnt[b];
            if (c == 1) {
                int s = g_bstart[b];
                g_rank[(int)(g_keys[s] & 0xFFFFFFFFu)] = s;
            } else if (c > 1) {
                int s = g_bstart[b];
                for (int a = 1; a < c; a++) {
                    u64 v = g_keys[s + a];
                    int q = a - 1;
                    while (q >= 0 && g_keys[s + q] > v) { g_keys[s + q + 1] = g_keys[s + q]; q--; }
                    g_keys[s + q + 1] = v;
                }
                for (int a = 0; a < c; a++)
                    g_rank[(int)(g_keys[s + a] & 0xFFFFFFFFu)] = s + a;
            }
        }
    }
    gridbar();

    // ================= P1: gather (coalesced by original idx) =================
    if (t < 256) {
        int idx = bid * 256 + t;
        int i = g_rank[idx];

        float b[9];
        #pragma unroll
        for (int c = 0; c < 9; c++) b[c] = pb[idx*9 + c];
        #pragma unroll
        for (int c = 0; c < 7; c++) { g_b7[i*7 + c] = b[c]; out[i*9 + c] = b[c]; }
        out[i*9 + 7] = b[7];
        out[i*9 + 8] = b[8];
        out[NN*9  + i] = ps[idx];
        int lab = pl[idx];
        out[NN*10 + i] = (float)lab;

        float h   = b[6];
        float ang = h - floorf(h / PI_F + 0.5f) * PI_F;
        bool  sw  = fabsf(ang) >= QPI_F;
        float dx  = sw ? b[4] : b[3];
        float dy  = sw ? b[3] : b[4];
        float4 bv;
        bv.x = b[0] - dx * 0.5f;
        bv.y = b[1] - dy * 0.5f;
        bv.z = b[0] + dx * 0.5f;
        bv.w = b[1] + dy * 0.5f;
        g_bev[i]  = bv;
        g_area[i] = dx * dy;

        int cx = (int)floorf((b[0] + 70.0f) * (1.0f / 4.5f)); cx = min(max(cx, 0), NX-1);
        int cy = (int)floorf((b[1] + 40.0f) * (1.0f / 4.5f)); cy = min(max(cy, 0), NY-1);
        int cell = (lab * NY + cy) * NX + cx;
        g_cellid[i] = cell;
        int pos = atomicAdd(&g_cellcnt[cell], 1);
        if (pos < CAPC) g_cellbox[cell*CAPC + pos] = (u16)i;
    }
    gridbar();

    // ================= P2: build pred/succ lists =================
    if (t < 256) {
        int i = bid * 256 + t;
        float4 a = g_bev[i];
        float aa = g_area[i];
        int cell = g_cellid[i];
        int cx = cell % NX, cy = (cell / NX) % NY, lab = cell / (NX * NY);
        int np = 0, ns = 0;
        for (int dy = -1; dy <= 1; dy++) {
            int yy = cy + dy; if (yy < 0 || yy >= NY) continue;
            for (int dx = -1; dx <= 1; dx++) {
                int xx = cx + dx; if (xx < 0 || xx >= NX) continue;
                int c2 = (lab * NY + yy) * NX + xx;
                int cnt2 = min(g_cellcnt[c2], CAPC);
                #pragma unroll 2
                for (int p = 0; p < cnt2; p++) {
                    int j = g_cellbox[c2*CAPC + p];
                    if (j == i) continue;
                    float4 bb = g_bev[j];
                    float ix = fminf(a.z, bb.z) - fmaxf(a.x, bb.x);
                    float iy = fminf(a.w, bb.w) - fmaxf(a.y, bb.y);
                    float inter = fmaxf(ix, 0.0f) * fmaxf(iy, 0.0f);
                    float uni   = aa + g_area[j] - inter;
                    if (inter > IOUT * fmaxf(uni, 1e-6f)) {
                        if (j < i) { if (np < CAP) g_pred[i*CAP + np++] = (u16)j; }
                        else       { if (ns < CAP) g_succ[i*CAP + ns++] = (u16)j; }
                    }
                }
            }
        }
        for (int a2 = 1; a2 < ns; a2++) {
            u16 v = g_succ[i*CAP + a2];
            int b = a2 - 1;
            while (b >= 0 && g_succ[i*CAP + b] > v) { g_succ[i*CAP + b + 1] = g_succ[i*CAP + b]; b--; }
            g_succ[i*CAP + b + 1] = v;
        }
        g_npred[i] = np;
        g_nsucc[i] = ns;
    }
    gridbar();

    // ================= P3: fixpoint + suppby + worklist (block 0 only) =========
    if (bid == 0) {
        int* offs = (int*)(sm + F_OFFS);
        u16* pd   = (u16*)(sm + F_PD);
        u8*  sts  = (u8*)(sm + F_STS);
        u16* sby  = (u16*)(sm + F_SBY);
        u16* fl0  = (u16*)(sm + F_FL0);
        u16* fl1  = (u16*)(sm + F_FL1);
        volatile u8* st = sts;
        const int base = t * 4;
        const int vt = g_vt;

        // CSR offsets from npred
        int np4[4]; int s0 = 0;
        #pragma unroll
        for (int k = 0; k < 4; k++) { np4[k] = g_npred[base + k]; s0 += np4[k]; }
        temp[t] = s0;
        __syncthreads();
        for (int off = 1; off < NT; off <<= 1) {
            int v = (t >= off) ? temp[t - off] : 0;
            __syncthreads();
            temp[t] += v;
            __syncthreads();
        }
        int run = (t == 0) ? 0 : temp[t - 1];
        #pragma unroll
        for (int k = 0; k < 4; k++) { offs[base + k] = run; run += np4[k]; }
        if (t == NT-1) offs[NN] = run;
        if (t == 0) s_useg = 0;
        __syncthreads();
        if (t == 0 && offs[NN] > SCAP) s_useg = 1;
        __syncthreads();
        if (!s_useg) {
            #pragma unroll
            for (int k = 0; k < 4; k++) {
                int i = base + k, o = offs[i];
                for (int p = 0; p < np4[k]; p++) pd[o + p] = g_pred[i*CAP + p];
            }
        }
        for (int i = t; i < NN; i += NT) sts[i] = (i < vt) ? 0 : 3;
        for (int i = t; i < vt; i += NT) fl0[i] = (u16)i;
        if (t == 0) s_nf = vt;
        __syncthreads();
        const int useg = s_useg;

        // frontier-compacted chaotic relaxation
        u16* cur = fl0; u16* nxt = fl1;
        for (int round = 0; round < NN; round++) {
            int nf = s_nf;
            if (nf <= 0) break;
            if (t == 0) s_nn = 0;
            __syncthreads();
            for (int k = t; k < nf; k += NT) {
                int i = cur[k];
                int o = offs[i], np = offs[i+1] - o;
                bool anyK = false, allS = true;
                for (int p = 0; p < np; p++) {
                    int j = useg ? (int)g_pred[i*CAP + p] : (int)pd[o + p];
                    u8 s = st[j];
                    anyK |= (s == 1);
                    allS &= (s >= 2);
                }
                if (anyK)      st[i] = 2;
                else if (allS) st[i] = 1;
                else { int pos = atomicAdd(&s_nn, 1); nxt[pos] = (u16)i; }
            }
            __syncthreads();
            if (t == 0) s_nf = s_nn;
            u16* tmpp = cur; cur = nxt; nxt = tmpp;
            __syncthreads();
        }

        // suppby + keep flags
        for (int i = t; i < NN; i += NT) {
            u8 s = sts[i];
            out[NN*11 + i] = (s == 1) ? 1.0f : 0.0f;
            u16 sb;
            if (s == 1) sb = (u16)i;
            else if (s == 3) sb = 0xFFFF;
            else {
                int o = offs[i], np = offs[i+1] - o;
                int best = 0xFFFF;
                for (int p = 0; p < np; p++) {
                    int q = useg ? (int)g_pred[i*CAP + p] : (int)pd[o + p];
                    if (sts[q] == 1 && q < best) best = q;
                }
                sb = (u16)best;
            }
            sby[i] = sb;
        }
        __syncthreads();

        // worklist of kept clusters with >1 member
        for (int i = t; i < NN; i += NT) {
            if (sts[i] != 1) continue;
            int ns = g_nsucc[i];
            u16 mem[MM];
            mem[0] = (u16)i;
            int cnt = 1, total = 1;
            for (int a = 0; a < ns; a++) {
                int j = g_succ[i*CAP + a];
                if ((int)sby[j] == i) { total++; if (cnt < MM) mem[cnt++] = (u16)j; }
            }
            if (total > 1) {
                int w = atomicAdd(&g_nwork, 1);
                g_work[w] = i;
                g_wcnt[w] = cnt;
                #pragma unroll
                for (int m = 0; m < MM; m++) if (m < cnt) g_wmem[w*MM + m] = mem[m];
            }
        }
    }
    gridbar();

    // ================= P4: merge MLP, one thread per (cluster, channel) ========
    {
        int gt = bid * NT + t;
        int w  = gt >> 3;
        int c  = gt & 7;
        if (c < 7 && w < g_nwork) {
            int i   = g_work[w];
            int cnt = g_wcnt[w];

            // prefetch member indices (independent loads, MLP)
            u16 midx[MM];
            #pragma unroll
            for (int m = 0; m < MM; m++) if (m < cnt) midx[m] = g_wmem[w*MM + m];
            // prefetch member channel values (independent loads, MLP)
            float xv[MM];
            #pragma unroll
            for (int m = 0; m < MM; m++) if (m < cnt) xv[m] = g_b7[(int)midx[m]*7 + c];

            float h1[HH];
            #pragma unroll
            for (int h = 0; h < HH; h++) h1[h] = s_b1[h];
            #pragma unroll
            for (int m = 0; m < MM; m++) {
                if (m < cnt) {
                    float v = xv[m];
                    #pragma unroll
                    for (int h = 0; h < HH; h++) h1[h] += v * s_w1[m*HH + h];
                }
            }
            #pragma unroll
            for (int h = 0; h < HH; h++) h1[h] = fmaxf(h1[h], 0.0f);
            float h2[HH];
            #pragma unroll
            for (int q = 0; q < HH; q++) h2[q] = s_b2[q];
            #pragma unroll
            for (int h = 0; h < HH; h++) {
                float v = h1[h];
                #pragma unroll
                for (int q = 0; q < HH; q++) h2[q] += v * s_w2[h*HH + q];
            }
            float acc = s_b3v;
            #pragma unroll
            for (int q = 0; q < HH; q++) acc += fmaxf(h2[q], 0.0f) * s_w3[q];

            if (c >= 3 && c <= 5) acc = fmaxf(acc, 1e-5f);
            out[i*9 + c] = acc;
        }
    }
}

extern "C" void kernel_launch(void* const* d_in, const int* in_sizes, int n_in,
                              void* d_out, int out_size) {
    const float* pb = (const float*)d_in[0];
    const float* ps = (const float*)d_in[1];
    const int*   pl = (const int*)  d_in[2];
    const float* w1 = (const float*)d_in[3];
    const float* b1 = (const float*)d_in[4];
    const float* w2 = (const float*)d_in[5];
    const float* b2 = (const float*)d_in[6];
    const float* w3 = (const float*)d_in[7];
    const float* b3 = (const float*)d_in[8];
    float* out = (float*)d_out;

    cudaFuncSetAttribute(k_all, cudaFuncAttributeMaxDynamicSharedMemorySize, SMEM_DYN);
    k_all<<<NB, NT, SMEM_DYN>>>(pb, ps, pl, w1, b1, w2, b2, w3, b3, out);
}

// round 10
// speedup vs baseline: 1.1037x; 1.1037x over previous
#include <cuda_runtime.h>
#include <math.h>

typedef unsigned long long u64;
typedef unsigned short u16;
typedef unsigned char u8;

#define NN 4096
#define MM 20
#define HH 16
#define NX 32
#define NY 18
#define NLAB 3
#define NCELL (NLAB*NX*NY)   /* 1728 */
#define CAP 64
#define CAPC 28
#define SCAP 24576           /* shared CSR capacity (entries) */
#define PI_F 3.14159274101257324f
#define QPI_F 0.785398185253143311f
#define COND 0.2f
#define IOUT 0.3f

// ---------------- global scratch (no allocations allowed) ----------------
__device__ int    g_rank[NN];         // original idx -> sorted pos
__device__ int    g_vt;               // number of valid boxes
__device__ float  g_b7[NN*7];
__device__ float4 g_bev[NN];
__device__ float  g_area[NN];
__device__ int    g_cellid[NN];
__device__ int    g_cellcnt[NCELL];
__device__ u16    g_cellbox[NCELL*CAPC];
__device__ u16    g_pred[NN*CAP];
__device__ u16    g_succ[NN*CAP];
__device__ int    g_npred[NN], g_nsucc[NN];
__device__ int    g_nwork;
__device__ int    g_work[2048];
__device__ int    g_wcnt[2048];
__device__ u16    g_wmem[2048*MM];

// ============ 1) single-block sort: only reads scores, writes rank ============
#define OFF_KEYS  0         /* u64[4096] 32KB */
#define OFF_CNT   32768     /* int[4096] 16KB */
#define OFF_START 49152     /* int[4096] 16KB */
#define OFF_TEMP  65536     /* int[1024]  4KB */
#define SMEM_A    69632

__global__ __launch_bounds__(1024) void k_sort(const float* __restrict__ ps)
{
    extern __shared__ char sm[];
    u64* keys   = (u64*)(sm + OFF_KEYS);
    int* bcnt   = (int*)(sm + OFF_CNT);
    int* bstart = (int*)(sm + OFF_START);
    int* temp   = (int*)(sm + OFF_TEMP);

    const int t = threadIdx.x;
    const int base = t * 4;
    if (t == 0) g_nwork = 0;
    for (int c = t; c < NCELL; c += 1024) g_cellcnt[c] = 0;

    for (int b = t; b < NN; b += 1024) bcnt[b] = 0;
    __syncthreads();

    unsigned keyv[4]; int bk[4]; int invc = 0;
    #pragma unroll
    for (int k = 0; k < 4; k++) {
        int i = base + k;
        float f = ps[i];
        if (f > COND) {
            unsigned u = __float_as_uint(f) | 0x80000000u;
            keyv[k] = ~u;                            // ascending key == descending f
            int b = 4096 - (int)(f * 4096.0f);
            b = min(max(b, 0), 4095);
            bk[k] = b;
            atomicAdd(&bcnt[b], 1);
        } else { bk[k] = -1; invc++; }
    }
    __syncthreads();

    // exclusive scan over 4096 buckets
    int myc[4]; int s0 = 0;
    #pragma unroll
    for (int k = 0; k < 4; k++) { myc[k] = bcnt[base + k]; s0 += myc[k]; }
    temp[t] = s0;
    __syncthreads();
    for (int off = 1; off < 1024; off <<= 1) {
        int v = (t >= off) ? temp[t - off] : 0;
        __syncthreads();
        temp[t] += v;
        __syncthreads();
    }
    int vt = temp[1023];
    if (t == 0) g_vt = vt;
    int run = (t == 0) ? 0 : temp[t - 1];
    #pragma unroll
    for (int k = 0; k < 4; k++) { bstart[base + k] = run; run += myc[k]; }
    __syncthreads();

    // invalid rank prefix (stable by original index)
    temp[t] = invc;
    __syncthreads();
    for (int off = 1; off < 1024; off <<= 1) {
        int v = (t >= off) ? temp[t - off] : 0;
        __syncthreads();
        temp[t] += v;
        __syncthreads();
    }
    int invBase = vt + ((t == 0) ? 0 : temp[t - 1]);

    // scatter
    int li = 0;
    #pragma unroll
    for (int k = 0; k < 4; k++) {
        int i = base + k;
        if (bk[k] >= 0) {
            int pos = atomicAdd(&bstart[bk[k]], 1);
            keys[pos] = ((u64)keyv[k] << 32) | (unsigned)i;
        } else {
            keys[invBase + li] = 0xFFFFFFFF00000000ull | (unsigned)i;
            li++;
        }
    }
    __syncthreads();

    // per-bucket insertion sort (segment = [bstart[b]-bcnt[b], bstart[b]))
    for (int b = t; b < NN; b += 1024) {
        int c = bcnt[b];
        if (c > 1) {
            int s = bstart[b] - c;
            for (int a = 1; a < c; a++) {
                u64 v = keys[s + a];
                int q = a - 1;
                while (q >= 0 && keys[s + q] > v) { keys[s + q + 1] = keys[s + q]; q--; }
                keys[s + q + 1] = v;
            }
        }
    }
    __syncthreads();

    // write inverse permutation
    #pragma unroll
    for (int k = 0; k < 4; k++) {
        int i = base + k;
        int idx = (int)(keys[i] & 0xFFFFFFFFu);
        g_rank[idx] = i;
    }
}

// ============ 2) multi-block gather: coalesced reads by original idx ============
__global__ __launch_bounds__(256) void k_gather(
    const float* __restrict__ pb, const float* __restrict__ ps,
    const int* __restrict__ pl, float* __restrict__ out)
{
    int idx = blockIdx.x * 256 + threadIdx.x;
    if (idx >= NN) return;
    int i = g_rank[idx];

    float b[9];
    #pragma unroll
    for (int c = 0; c < 9; c++) b[c] = pb[idx*9 + c];
    #pragma unroll
    for (int c = 0; c < 7; c++) { g_b7[i*7 + c] = b[c]; out[i*9 + c] = b[c]; }
    out[i*9 + 7] = b[7];
    out[i*9 + 8] = b[8];
    out[NN*9  + i] = ps[idx];
    int lab = pl[idx];
    out[NN*10 + i] = (float)lab;

    float h   = b[6];
    float ang = h - floorf(h / PI_F + 0.5f) * PI_F;
    bool  sw  = fabsf(ang) >= QPI_F;
    float dx  = sw ? b[4] : b[3];
    float dy  = sw ? b[3] : b[4];
    float4 bv;
    bv.x = b[0] - dx * 0.5f;
    bv.y = b[1] - dy * 0.5f;
    bv.z = b[0] + dx * 0.5f;
    bv.w = b[1] + dy * 0.5f;
    g_bev[i]  = bv;
    g_area[i] = dx * dy;

    int cx = (int)floorf((b[0] + 70.0f) * (1.0f / 4.5f)); cx = min(max(cx, 0), NX-1);
    int cy = (int)floorf((b[1] + 40.0f) * (1.0f / 4.5f)); cy = min(max(cy, 0), NY-1);
    int cell = (lab * NY + cy) * NX + cx;
    g_cellid[i] = cell;
    int pos = atomicAdd(&g_cellcnt[cell], 1);
    if (pos < CAPC) g_cellbox[cell*CAPC + pos] = (u16)i;
}

// ============ 3) multi-block: build overlap pred/succ lists ============
__global__ __launch_bounds__(256) void k_build() {
    int i = blockIdx.x * 256 + threadIdx.x;
    if (i >= NN) return;
    float4 a = g_bev[i];
    float aa = g_area[i];
    int cell = g_cellid[i];
    int cx = cell % NX, cy = (cell / NX) % NY, lab = cell / (NX * NY);
    int np = 0, ns = 0;
    for (int dy = -1; dy <= 1; dy++) {
        int yy = cy + dy; if (yy < 0 || yy >= NY) continue;
        for (int dx = -1; dx <= 1; dx++) {
            int xx = cx + dx; if (xx < 0 || xx >= NX) continue;
            int c2 = (lab * NY + yy) * NX + xx;
            int cnt2 = min(g_cellcnt[c2], CAPC);
            for (int p = 0; p < cnt2; p++) {
                int j = g_cellbox[c2*CAPC + p];
                if (j == i) continue;
                float4 bb = g_bev[j];
                float ix = fminf(a.z, bb.z) - fmaxf(a.x, bb.x);
                float iy = fminf(a.w, bb.w) - fmaxf(a.y, bb.y);
                float inter = fmaxf(ix, 0.0f) * fmaxf(iy, 0.0f);
                float uni   = aa + g_area[j] - inter;
                if (inter > IOUT * fmaxf(uni, 1e-6f)) {
                    if (j < i) { if (np < CAP) g_pred[i*CAP + np++] = (u16)j; }
                    else       { if (ns < CAP) g_succ[i*CAP + ns++] = (u16)j; }
                }
            }
        }
    }
    // succ ascending (cluster member order)
    for (int a2 = 1; a2 < ns; a2++) {
        u16 v = g_succ[i*CAP + a2];
        int b = a2 - 1;
        while (b >= 0 && g_succ[i*CAP + b] > v) { g_succ[i*CAP + b + 1] = g_succ[i*CAP + b]; b--; }
        g_succ[i*CAP + b + 1] = v;
    }
    g_npred[i] = np;
    g_nsucc[i] = ns;
}

// ============ 4) single-block: frontier fixpoint + suppby + worklist ============
// dynamic shared layout
#define F_OFFS  0           /* int[4097] 16388 -> pad to 16392 */
#define F_PD    16392       /* u16[SCAP] 49152 */
#define F_STS   65544       /* u8[4096]  4096 */
#define F_SBY   69640       /* u16[4096] 8192 */
#define F_FL0   77832       /* u16[4096] 8192 */
#define F_FL1   86024       /* u16[4096] 8192 */
#define F_TMP   94216       /* int[1024] 4096 */
#define SMEM_F  98312

__global__ __launch_bounds__(1024) void k_fix(float* __restrict__ out) {
    extern __shared__ char sm[];
    int* offs = (int*)(sm + F_OFFS);
    u16* pd   = (u16*)(sm + F_PD);
    u8*  sts  = (u8*)(sm + F_STS);
    u16* sby  = (u16*)(sm + F_SBY);
    u16* fl0  = (u16*)(sm + F_FL0);
    u16* fl1  = (u16*)(sm + F_FL1);
    int* temp = (int*)(sm + F_TMP);
    __shared__ int s_useg, s_nf, s_nn;
    volatile u8* st = sts;
    const int t = threadIdx.x;
    const int base = t * 4;
    const int vt = g_vt;

    // CSR offsets from npred
    int np4[4]; int s0 = 0;
    #pragma unroll
    for (int k = 0; k < 4; k++) { np4[k] = g_npred[base + k]; s0 += np4[k]; }
    temp[t] = s0;
    __syncthreads();
    for (int off = 1; off < 1024; off <<= 1) {
        int v = (t >= off) ? temp[t - off] : 0;
        __syncthreads();
        temp[t] += v;
        __syncthreads();
    }
    int run = (t == 0) ? 0 : temp[t - 1];
    #pragma unroll
    for (int k = 0; k < 4; k++) { offs[base + k] = run; run += np4[k]; }
    if (t == 1023) offs[NN] = run;
    if (t == 0) s_useg = 0;
    __syncthreads();
    if (t == 0 && offs[NN] > SCAP) s_useg = 1;
    __syncthreads();
    if (!s_useg) {
        #pragma unroll
        for (int k = 0; k < 4; k++) {
            int i = base + k, o = offs[i];
            for (int p = 0; p < np4[k]; p++) pd[o + p] = g_pred[i*CAP + p];
        }
    }
    for (int i = t; i < NN; i += 1024) sts[i] = (i < vt) ? 0 : 3;
    for (int i = t; i < vt; i += 1024) fl0[i] = (u16)i;
    if (t == 0) s_nf = vt;
    __syncthreads();
    const int useg = s_useg;

    // frontier-compacted chaotic relaxation
    u16* cur = fl0; u16* nxt = fl1;
    for (int round = 0; round < NN; round++) {
        int nf = s_nf;
        if (nf <= 0) break;
        if (t == 0) s_nn = 0;
        __syncthreads();
        for (int k = t; k < nf; k += 1024) {
            int i = cur[k];
            int o = offs[i], np = offs[i+1] - o;
            bool anyK = false, allS = true;
            for (int p = 0; p < np; p++) {
                int j = useg ? (int)g_pred[i*CAP + p] : (int)pd[o + p];
                u8 s = st[j];
                anyK |= (s == 1);
                allS &= (s >= 2);
            }
            if (anyK)      st[i] = 2;
            else if (allS) st[i] = 1;
            else { int pos = atomicAdd(&s_nn, 1); nxt[pos] = (u16)i; }
        }
        __syncthreads();
        if (t == 0) s_nf = s_nn;
        u16* tmpp = cur; cur = nxt; nxt = tmpp;
        __syncthreads();
    }

    // suppby + keep flags
    for (int i = t; i < NN; i += 1024) {
        u8 s = sts[i];
        out[NN*11 + i] = (s == 1) ? 1.0f : 0.0f;
        u16 sb;
        if (s == 1) sb = (u16)i;
        else if (s == 3) sb = 0xFFFF;
        else {
            int o = offs[i], np = offs[i+1] - o;
            int best = 0xFFFF;
            for (int p = 0; p < np; p++) {
                int q = useg ? (int)g_pred[i*CAP + p] : (int)pd[o + p];
                if (sts[q] == 1 && q < best) best = q;
            }
            sb = (u16)best;
        }
        sby[i] = sb;
    }
    __syncthreads();

    // worklist of kept clusters with >1 member
    for (int i = t; i < NN; i += 1024) {
        if (sts[i] != 1) continue;
        int ns = g_nsucc[i];
        u16 mem[MM];
        mem[0] = (u16)i;
        int cnt = 1, total = 1;
        for (int a = 0; a < ns; a++) {
            int j = g_succ[i*CAP + a];
            if ((int)sby[j] == i) { total++; if (cnt < MM) mem[cnt++] = (u16)j; }
        }
        if (total > 1) {
            int w = atomicAdd(&g_nwork, 1);
            g_work[w] = i;
            g_wcnt[w] = cnt;
            #pragma unroll
            for (int m = 0; m < MM; m++) if (m < cnt) g_wmem[w*MM + m] = mem[m];
        }
    }
}

// ============ 5) merge MLP: one thread per (cluster, channel), prefetched ============
__global__ __launch_bounds__(256) void k_merge(
    const float* __restrict__ w1, const float* __restrict__ b1,
    const float* __restrict__ w2, const float* __restrict__ b2,
    const float* __restrict__ w3, const float* __restrict__ b3,
    float* __restrict__ out)
{
    __shared__ float s_w1[MM*HH], s_w2[HH*HH], s_w3[HH], s_b1[HH], s_b2[HH], s_b3;
    const int t = threadIdx.x;
    for (int k = t; k < MM*HH; k += 256) s_w1[k] = w1[k];
    for (int k = t; k < HH*HH; k += 256) s_w2[k] = w2[k];
    if (t < HH) { s_w3[t] = w3[t]; s_b1[t] = b1[t]; s_b2[t] = b2[t]; }
    if (t == 0) s_b3 = b3[0];
    __syncthreads();

    int gt = blockIdx.x * 256 + t;
    int w  = gt >> 3;
    int c  = gt & 7;
    if (c >= 7 || w >= g_nwork) return;

    int i   = g_work[w];
    int cnt = g_wcnt[w];

    // prefetch member indices, then values (independent loads, high MLP)
    u16 midx[MM];
    #pragma unroll
    for (int m = 0; m < MM; m++) if (m < cnt) midx[m] = g_wmem[w*MM + m];
    float xv[MM];
    #pragma unroll
    for (int m = 0; m < MM; m++) if (m < cnt) xv[m] = g_b7[(int)midx[m]*7 + c];

    float h1[HH];
    #pragma unroll
    for (int h = 0; h < HH; h++) h1[h] = s_b1[h];
    #pragma unroll
    for (int m = 0; m < MM; m++) {
        if (m < cnt) {
            float v = xv[m];
            #pragma unroll
            for (int h = 0; h < HH; h++) h1[h] += v * s_w1[m*HH + h];
        }
    }
    #pragma unroll
    for (int h = 0; h < HH; h++) h1[h] = fmaxf(h1[h], 0.0f);
    float h2[HH];
    #pragma unroll
    for (int q = 0; q < HH; q++) h2[q] = s_b2[q];
    #pragma unroll
    for (int h = 0; h < HH; h++) {
        float v = h1[h];
        #pragma unroll
        for (int q = 0; q < HH; q++) h2[q] += v * s_w2[h*HH + q];
    }
    float acc = s_b3;
    #pragma unroll
    for (int q = 0; q < HH; q++) acc += fmaxf(h2[q], 0.0f) * s_w3[q];

    if (c >= 3 && c <= 5) acc = fmaxf(acc, 1e-5f);
    out[i*9 + c] = acc;
}

extern "C" void kernel_launch(void* const* d_in, const int* in_sizes, int n_in,
                              void* d_out, int out_size) {
    const float* pb = (const float*)d_in[0];
    const float* ps = (const float*)d_in[1];
    const int*   pl = (const int*)  d_in[2];
    const float* w1 = (const float*)d_in[3];
    const float* b1 = (const float*)d_in[4];
    const float* w2 = (const float*)d_in[5];
    const float* b2 = (const float*)d_in[6];
    const float* w3 = (const float*)d_in[7];
    const float* b3 = (const float*)d_in[8];
    float* out = (float*)d_out;

    cudaFuncSetAttribute(k_sort, cudaFuncAttributeMaxDynamicSharedMemorySize, SMEM_A);
    cudaFuncSetAttribute(k_fix,  cudaFuncAttributeMaxDynamicSharedMemorySize, SMEM_F);
    k_sort<<<1, 1024, SMEM_A>>>(ps);
    k_gather<<<16, 256>>>(pb, ps, pl, out);
    k_build<<<16, 256>>>();
    k_fix<<<1, 1024, SMEM_F>>>(out);
    k_merge<<<64, 256>>>(w1, b1, w2, b2, w3, b3, out);
}

// round 11
// speedup vs baseline: 1.2210x; 1.1063x over previous
#include <cuda_runtime.h>
#include <math.h>

typedef unsigned long long u64;
typedef unsigned short u16;
typedef unsigned char u8;

#define NN 4096
#define MM 20
#define HH 16
#define NX 32
#define NY 18
#define NLAB 3
#define NCELL (NLAB*NX*NY)   /* 1728 */
#define CAP 64
#define CAPC 28
#define SCAP 24576           /* shared CSR capacity (entries) */
#define PI_F 3.14159274101257324f
#define QPI_F 0.785398185253143311f
#define COND 0.2f
#define IOUT 0.3f

// ---------------- global scratch (no allocations allowed) ----------------
__device__ int    g_rank[NN];
__device__ int    g_vt;
__device__ float  g_b7[NN*7];
__device__ float4 g_bev[NN];
__device__ float  g_area[NN];
__device__ int    g_cellid[NN];
__device__ int    g_cellcnt[NCELL];
__device__ u16    g_cellbox[NCELL*CAPC];
__device__ u16    g_pred[NN*CAP];
__device__ u16    g_succ[NN*CAP];
__device__ int    g_npred[NN], g_nsucc[NN];
__device__ u8     g_sts[NN];          // 1=kept 2=suppressed 3=invalid
__device__ u16    g_sby[NN];          // suppressor (self if kept, 0xFFFF invalid)

// ---------------- warp-shuffle inclusive scan ----------------
__device__ __forceinline__ int warp_iscan(int v, int lane) {
    #pragma unroll
    for (int o = 1; o < 32; o <<= 1) {
        int n = __shfl_up_sync(0xFFFFFFFFu, v, o);
        if (lane >= o) v += n;
    }
    return v;
}

// ============ 1) single-block sort: reads scores, writes rank ============
#define OFF_KEYS  0         /* u64[4096] 32KB */
#define OFF_CNT   32768     /* int[4096] 16KB */
#define OFF_START 49152     /* int[4096] 16KB */
#define OFF_TEMP  65536     /* int[32]  128B  */
#define SMEM_A    65664

__global__ __launch_bounds__(1024) void k_sort(const float* __restrict__ ps)
{
    extern __shared__ char sm[];
    u64* keys   = (u64*)(sm + OFF_KEYS);
    int* bcnt   = (int*)(sm + OFF_CNT);
    int* bstart = (int*)(sm + OFF_START);
    int* temp   = (int*)(sm + OFF_TEMP);

    const int t = threadIdx.x;
    const int lane = t & 31;
    const int wid  = t >> 5;
    const int base = t * 4;

    for (int c = t; c < NCELL; c += 1024) g_cellcnt[c] = 0;
    for (int b = t; b < NN; b += 1024) bcnt[b] = 0;
    __syncthreads();

    unsigned keyv[4]; int bk[4]; int invc = 0;
    #pragma unroll
    for (int k = 0; k < 4; k++) {
        int i = base + k;
        float f = ps[i];
        if (f > COND) {
            unsigned u = __float_as_uint(f) | 0x80000000u;
            keyv[k] = ~u;                           // ascending key == descending f
            int b = 4096 - (int)(f * 4096.0f);
            b = min(max(b, 0), 4095);
            bk[k] = b;
            atomicAdd(&bcnt[b], 1);
        } else { bk[k] = -1; invc++; }
    }
    __syncthreads();

    // packed scan: low 16 = bucket-count sums, high 16 = invalid counts
    int myc[4]; int s0 = 0;
    #pragma unroll
    for (int k = 0; k < 4; k++) { myc[k] = bcnt[base + k]; s0 += myc[k]; }
    int packed = s0 | (invc << 16);
    int incl = warp_iscan(packed, lane);
    if (lane == 31) temp[wid] = incl;
    __syncthreads();
    if (t < 32) temp[t] = warp_iscan(temp[t], t);
    __syncthreads();
    int pre = (wid > 0) ? temp[wid - 1] : 0;
    incl += pre;
    int tot = temp[31];
    int vt  = tot & 0xFFFF;
    if (t == 0) g_vt = vt;
    int excl = incl - packed;
    int run     = excl & 0xFFFF;          // exclusive prefix of bucket counts
    int invPre  = (excl >> 16) & 0xFFFF;  // exclusive prefix of invalid counts
    #pragma unroll
    for (int k = 0; k < 4; k++) { bstart[base + k] = run; run += myc[k]; }
    int invBase = vt + invPre;
    __syncthreads();

    // scatter
    int li = 0;
    #pragma unroll
    for (int k = 0; k < 4; k++) {
        int i = base + k;
        if (bk[k] >= 0) {
            int pos = atomicAdd(&bstart[bk[k]], 1);
            keys[pos] = ((u64)keyv[k] << 32) | (unsigned)i;
        } else {
            keys[invBase + li] = 0xFFFFFFFF00000000ull | (unsigned)i;
            li++;
        }
    }
    __syncthreads();

    // per-bucket insertion sort (segment = [bstart[b]-bcnt[b], bstart[b]))
    for (int b = t; b < NN; b += 1024) {
        int c = bcnt[b];
        if (c > 1) {
            int s = bstart[b] - c;
            for (int a = 1; a < c; a++) {
                u64 v = keys[s + a];
                int q = a - 1;
                while (q >= 0 && keys[s + q] > v) { keys[s + q + 1] = keys[s + q]; q--; }
                keys[s + q + 1] = v;
            }
        }
    }
    __syncthreads();

    // inverse permutation
    #pragma unroll
    for (int k = 0; k < 4; k++) {
        int i = base + k;
        g_rank[(int)(keys[i] & 0xFFFFFFFFu)] = i;
    }
}

// ============ 2) multi-block gather ============
__global__ __launch_bounds__(256) void k_gather(
    const float* __restrict__ pb, const float* __restrict__ ps,
    const int* __restrict__ pl, float* __restrict__ out)
{
    int idx = blockIdx.x * 256 + threadIdx.x;
    if (idx >= NN) return;
    int i = g_rank[idx];

    float b[9];
    #pragma unroll
    for (int c = 0; c < 9; c++) b[c] = pb[idx*9 + c];
    #pragma unroll
    for (int c = 0; c < 7; c++) { g_b7[i*7 + c] = b[c]; out[i*9 + c] = b[c]; }
    out[i*9 + 7] = b[7];
    out[i*9 + 8] = b[8];
    out[NN*9  + i] = ps[idx];
    int lab = pl[idx];
    out[NN*10 + i] = (float)lab;

    float h   = b[6];
    float ang = h - floorf(h / PI_F + 0.5f) * PI_F;
    bool  sw  = fabsf(ang) >= QPI_F;
    float dx  = sw ? b[4] : b[3];
    float dy  = sw ? b[3] : b[4];
    float4 bv;
    bv.x = b[0] - dx * 0.5f;
    bv.y = b[1] - dy * 0.5f;
    bv.z = b[0] + dx * 0.5f;
    bv.w = b[1] + dy * 0.5f;
    g_bev[i]  = bv;
    g_area[i] = dx * dy;

    int cx = (int)floorf((b[0] + 70.0f) * (1.0f / 4.5f)); cx = min(max(cx, 0), NX-1);
    int cy = (int)floorf((b[1] + 40.0f) * (1.0f / 4.5f)); cy = min(max(cy, 0), NY-1);
    int cell = (lab * NY + cy) * NX + cx;
    g_cellid[i] = cell;
    int pos = atomicAdd(&g_cellcnt[cell], 1);
    if (pos < CAPC) g_cellbox[cell*CAPC + pos] = (u16)i;
}

// ============ 3) multi-block: build overlap pred/succ lists ============
__global__ __launch_bounds__(256) void k_build() {
    int i = blockIdx.x * 256 + threadIdx.x;
    if (i >= NN) return;
    float4 a = g_bev[i];
    float aa = g_area[i];
    int cell = g_cellid[i];
    int cx = cell % NX, cy = (cell / NX) % NY, lab = cell / (NX * NY);
    int np = 0, ns = 0;
    for (int dy = -1; dy <= 1; dy++) {
        int yy = cy + dy; if (yy < 0 || yy >= NY) continue;
        for (int dx = -1; dx <= 1; dx++) {
            int xx = cx + dx; if (xx < 0 || xx >= NX) continue;
            int c2 = (lab * NY + yy) * NX + xx;
            int cnt2 = min(g_cellcnt[c2], CAPC);
            for (int p = 0; p < cnt2; p++) {
                int j = g_cellbox[c2*CAPC + p];
                if (j == i) continue;
                float4 bb = g_bev[j];
                float ix = fminf(a.z, bb.z) - fmaxf(a.x, bb.x);
                float iy = fminf(a.w, bb.w) - fmaxf(a.y, bb.y);
                float inter = fmaxf(ix, 0.0f) * fmaxf(iy, 0.0f);
                float uni   = aa + g_area[j] - inter;
                if (inter > IOUT * fmaxf(uni, 1e-6f)) {
                    if (j < i) { if (np < CAP) g_pred[i*CAP + np++] = (u16)j; }
                    else       { if (ns < CAP) g_succ[i*CAP + ns++] = (u16)j; }
                }
            }
        }
    }
    for (int a2 = 1; a2 < ns; a2++) {
        u16 v = g_succ[i*CAP + a2];
        int b = a2 - 1;
        while (b >= 0 && g_succ[i*CAP + b] > v) { g_succ[i*CAP + b + 1] = g_succ[i*CAP + b]; b--; }
        g_succ[i*CAP + b + 1] = v;
    }
    g_npred[i] = np;
    g_nsucc[i] = ns;
}

// ============ 4) single-block: fixpoint + suppby (publish sts/sby) ============
#define F_OFFS  0           /* int[4097] -> pad to 16392 */
#define F_PD    16392       /* u16[SCAP] 49152 */
#define F_STS   65544       /* u8[4096]  4096 */
#define F_FL0   69640       /* u16[4096] 8192 */
#define F_FL1   77832       /* u16[4096] 8192 */
#define F_TMP   86024       /* int[32]   128  */
#define SMEM_F  86152

__global__ __launch_bounds__(1024) void k_fix(float* __restrict__ out) {
    extern __shared__ char sm[];
    int* offs = (int*)(sm + F_OFFS);
    u16* pd   = (u16*)(sm + F_PD);
    u8*  sts  = (u8*)(sm + F_STS);
    u16* fl0  = (u16*)(sm + F_FL0);
    u16* fl1  = (u16*)(sm + F_FL1);
    int* temp = (int*)(sm + F_TMP);
    __shared__ int s_useg, s_nf, s_nn;
    volatile u8* st = sts;
    const int t = threadIdx.x;
    const int lane = t & 31;
    const int wid  = t >> 5;
    const int base = t * 4;
    const int vt = g_vt;

    // CSR offsets via warp-shuffle scan (2 barriers)
    int np4[4]; int s0 = 0;
    #pragma unroll
    for (int k = 0; k < 4; k++) { np4[k] = g_npred[base + k]; s0 += np4[k]; }
    int incl = warp_iscan(s0, lane);
    if (lane == 31) temp[wid] = incl;
    __syncthreads();
    if (t < 32) temp[t] = warp_iscan(temp[t], t);
    __syncthreads();
    int run = incl + ((wid > 0) ? temp[wid - 1] : 0) - s0;
    #pragma unroll
    for (int k = 0; k < 4; k++) { offs[base + k] = run; run += np4[k]; }
    if (t == 1023) offs[NN] = run;
    if (t == 0) { s_useg = (temp[31] > SCAP) ? 1 : 0; s_nf = vt; }
    __syncthreads();
    const int useg = s_useg;
    if (!useg) {
        #pragma unroll
        for (int k = 0; k < 4; k++) {
            int i = base + k, o = offs[i];
            for (int p = 0; p < np4[k]; p++) pd[o + p] = g_pred[i*CAP + p];
        }
    }
    for (int i = t; i < NN; i += 1024) sts[i] = (i < vt) ? 0 : 3;
    for (int i = t; i < vt; i += 1024) fl0[i] = (u16)i;
    __syncthreads();

    // frontier-compacted chaotic relaxation
    u16* cur = fl0; u16* nxt = fl1;
    for (int round = 0; round < NN; round++) {
        int nf = s_nf;
        if (nf <= 0) break;
        if (t == 0) s_nn = 0;
        __syncthreads();
        for (int k = t; k < nf; k += 1024) {
            int i = cur[k];
            int o = offs[i], np = offs[i+1] - o;
            bool anyK = false, allS = true;
            for (int p = 0; p < np; p++) {
                int j = useg ? (int)g_pred[i*CAP + p] : (int)pd[o + p];
                u8 s = st[j];
                anyK |= (s == 1);
                allS &= (s >= 2);
            }
            if (anyK)      st[i] = 2;
            else if (allS) st[i] = 1;
            else { int pos = atomicAdd(&s_nn, 1); nxt[pos] = (u16)i; }
        }
        __syncthreads();
        if (t == 0) s_nf = s_nn;
        u16* tmpp = cur; cur = nxt; nxt = tmpp;
        __syncthreads();
    }

    // publish status, suppby, keep flags
    for (int i = t; i < NN; i += 1024) {
        u8 s = sts[i];
        g_sts[i] = s;
        out[NN*11 + i] = (s == 1) ? 1.0f : 0.0f;
        u16 sb;
        if (s == 1) sb = (u16)i;
        else if (s == 3) sb = 0xFFFF;
        else {
            int o = offs[i], np = offs[i+1] - o;
            int best = 0xFFFF;
            for (int p = 0; p < np; p++) {
                int q = useg ? (int)g_pred[i*CAP + p] : (int)pd[o + p];
                if (sts[q] == 1 && q < best) best = q;
            }
            sb = (u16)best;
        }
        g_sby[i] = sb;
    }
}

// ============ 5) merge MLP: thread per (sorted idx, channel), self-built cluster ============
__global__ __launch_bounds__(256) void k_merge(
    const float* __restrict__ w1, const float* __restrict__ b1,
    const float* __restrict__ w2, const float* __restrict__ b2,
    const float* __restrict__ w3, const float* __restrict__ b3,
    float* __restrict__ out)
{
    __shared__ float s_w1[MM*HH], s_w2[HH*HH], s_w3[HH], s_b1[HH], s_b2[HH], s_b3;
    const int t = threadIdx.x;
    for (int k = t; k < MM*HH; k += 256) s_w1[k] = w1[k];
    for (int k = t; k < HH*HH; k += 256) s_w2[k] = w2[k];
    if (t < HH) { s_w3[t] = w3[t]; s_b1[t] = b1[t]; s_b2[t] = b2[t]; }
    if (t == 0) s_b3 = b3[0];
    __syncthreads();

    int gt = blockIdx.x * 256 + t;
    int i = gt >> 3;
    int c = gt & 7;
    if (c >= 7 || i >= NN) return;
    if (g_sts[i] != 1) return;

    // rebuild member list (succ sorted ascending; member iff suppressed-by == i)
    int ns = g_nsucc[i];
    u16 mem[MM];
    mem[0] = (u16)i;
    int cnt = 1, total = 1;
    for (int a = 0; a < ns; a++) {
        int j = g_succ[i*CAP + a];
        if ((int)g_sby[j] == i) { total++; if (cnt < MM) mem[cnt++] = (u16)j; }
    }
    if (total <= 1) return;   // baseline row already written by k_gather

    // prefetch member channel values (independent loads)
    float xv[MM];
    #pragma unroll
    for (int m = 0; m < MM; m++) if (m < cnt) xv[m] = g_b7[(int)mem[m]*7 + c];

    float h1[HH];
    #pragma unroll
    for (int h = 0; h < HH; h++) h1[h] = s_b1[h];
    #pragma unroll
    for (int m = 0; m < MM; m++) {
        if (m < cnt) {
            float v = xv[m];
            #pragma unroll
            for (int h = 0; h < HH; h++) h1[h] += v * s_w1[m*HH + h];
        }
    }
    #pragma unroll
    for (int h = 0; h < HH; h++) h1[h] = fmaxf(h1[h], 0.0f);
    float h2[HH];
    #pragma unroll
    for (int q = 0; q < HH; q++) h2[q] = s_b2[q];
    #pragma unroll
    for (int h = 0; h < HH; h++) {
        float v = h1[h];
        #pragma unroll
        for (int q = 0; q < HH; q++) h2[q] += v * s_w2[h*HH + q];
    }
    float acc = s_b3;
    #pragma unroll
    for (int q = 0; q < HH; q++) acc += fmaxf(h2[q], 0.0f) * s_w3[q];

    if (c >= 3 && c <= 5) acc = fmaxf(acc, 1e-5f);
    out[i*9 + c] = acc;
}

extern "C" void kernel_launch(void* const* d_in, const int* in_sizes, int n_in,
                              void* d_out, int out_size) {
    const float* pb = (const float*)d_in[0];
    const float* ps = (const float*)d_in[1];
    const int*   pl = (const int*)  d_in[2];
    const float* w1 = (const float*)d_in[3];
    const float* b1 = (const float*)d_in[4];
    const float* w2 = (const float*)d_in[5];
    const float* b2 = (const float*)d_in[6];
    const float* w3 = (const float*)d_in[7];
    const float* b3 = (const float*)d_in[8];
    float* out = (float*)d_out;

    cudaFuncSetAttribute(k_sort, cudaFuncAttributeMaxDynamicSharedMemorySize, SMEM_A);
    cudaFuncSetAttribute(k_fix,  cudaFuncAttributeMaxDynamicSharedMemorySize, SMEM_F);
    k_sort<<<1, 1024, SMEM_A>>>(ps);
    k_gather<<<16, 256>>>(pb, ps, pl, out);
    k_build<<<16, 256>>>();
    k_fix<<<1, 1024, SMEM_F>>>(out);
    k_merge<<<128, 256>>>(w1, b1, w2, b2, w3, b3, out);
}